// round 15
// baseline (speedup 1.0000x reference)
#include <cuda_runtime.h>
#include <cuda_fp16.h>

// Problem dims (fixed by dataset): N=30000, F=16, S=8, H=16, E=300000
#define NMAX 30080
#define PRE_BLOCKS 148

// g, j-major layout (uint view): gu[n*64 + j*8 + t] = half2 for (h=2j,2j+1), slice t
__device__ __half   g8[(size_t)NMAX * 128];
__device__ unsigned gbias[(size_t)NMAX * 8];
__device__ float    agg_buf[(size_t)NMAX * 16];
__device__ unsigned pooled_bits[16];   // raw float bits of max(relu(agg)) >= 0
__device__ unsigned finish_count;

__device__ __forceinline__ void mma16816(float d[4],
    unsigned a0, unsigned a1, unsigned a2, unsigned a3,
    unsigned b0, unsigned b1)
{
    float z = 0.0f;
    asm("mma.sync.aligned.m16n8k16.row.col.f32.f16.f16.f32 "
        "{%0,%1,%2,%3}, {%4,%5,%6,%7}, {%8,%9}, {%10,%11,%12,%13};"
        : "=f"(d[0]), "=f"(d[1]), "=f"(d[2]), "=f"(d[3])
        : "r"(a0), "r"(a1), "r"(a2), "r"(a3), "r"(b0), "r"(b1),
          "f"(z), "f"(z), "f"(z), "f"(z));
}

__device__ __forceinline__ unsigned f2h2(float lo, float hi)
{
    __half2 h = __floats2half2_rn(lo, hi);
    return *(unsigned*)&h;
}

// ---------------------------------------------------------------------------
// Kernel P (HMMA): g[N x 160] = x[N x 16] @ Wtilde[16 x 160], fp16 in/fp32 acc.
// 148 blocks x 16 warps; warp (b,w) handles slab b + 148w -> <= 1 slab each.
// A-frag loads hoisted ABOVE weight staging/sync (independent of smem);
// B-frags loaded just-in-time inside the MMA loop (each used exactly once).
// ---------------------------------------------------------------------------
struct AFrag { unsigned a0, a1, a2, a3; int na, nb; };

__device__ __forceinline__ AFrag load_afrag(const float2* X2, int n0, int r,
                                            int m, int N)
{
    AFrag f;
    f.na = n0 + r; f.nb = n0 + r + 8;
    int nac = (f.na < N) ? f.na : N - 1;
    int nbc = (f.nb < N) ? f.nb : N - 1;
    float2 xa0 = __ldg(X2 + (size_t)nac * 8 + m);
    float2 xa2 = __ldg(X2 + (size_t)nac * 8 + m + 4);
    float2 xa1 = __ldg(X2 + (size_t)nbc * 8 + m);
    float2 xa3 = __ldg(X2 + (size_t)nbc * 8 + m + 4);
    f.a0 = f2h2(xa0.x, xa0.y);
    f.a1 = f2h2(xa1.x, xa1.y);
    f.a2 = f2h2(xa2.x, xa2.y);
    f.a3 = f2h2(xa3.x, xa3.y);
    return f;
}

__global__ void __launch_bounds__(512) node_pre(const float* __restrict__ x,
                                                const float* __restrict__ Wk,
                                                const float* __restrict__ bk,
                                                const float* __restrict__ Wr,
                                                const float* __restrict__ br,
                                                int N)
{
    __shared__ __half Whs[160 * 18];                 // [c][f], stride 18 (pad)

    int tid = threadIdx.x;
    int w = tid >> 5;
    int l = tid & 31;
    int r = l >> 2;
    int m = l & 3;

    int nslabs = (N + 15) >> 4;
    const float2* X2 = (const float2*)x;

    // Hoisted A-frag load for this warp's (usually only) slab.
    int slab0 = blockIdx.x + PRE_BLOCKS * w;
    AFrag af;
    bool have = (slab0 < nslabs);
    if (have) af = load_afrag(X2, slab0 * 16, r, m, N);

    // Stage + convert weights (overlaps with the in-flight A loads).
    for (int i = tid; i < 2560; i += 512) {
        int c = i >> 4, f = i & 15;
        int t = c >> 4, h = c & 15;
        float v = (t < 8) ? Wk[t * 256 + f * 16 + h]
                : (t == 8) ? bk[f * 16 + h] : Wr[f * 16 + h];
        Whs[c * 18 + f] = __float2half_rn(v);
    }
    __syncthreads();

    float br0 = br[2 * m], br1 = br[2 * m + 1];
    float br8 = br[8 + 2 * m], br9 = br[9 + 2 * m];

    for (int slab = slab0; slab < nslabs; slab += PRE_BLOCKS * 16) {
        if (slab != slab0) af = load_afrag(X2, slab * 16, r, m, N);
        int na = af.na, nb = af.nb;

        unsigned outA[2][8], outB[2][8];

#pragma unroll
        for (int nt = 0; nt < 20; nt++) {
            // JIT B-frag load: col c = 8*nt + r, used once.
            int c = nt * 8 + r;
            unsigned b0 = *(const unsigned*)&Whs[c * 18 + 2 * m];
            unsigned b1 = *(const unsigned*)&Whs[c * 18 + 2 * m + 8];
            float d[4];
            mma16816(d, af.a0, af.a1, af.a2, af.a3, b0, b1);
            int jh = nt & 1;
            int j  = m + 4 * jh;
            if (nt < 16) {
                int t = nt >> 1;
                outA[jh][t] = f2h2(d[0], d[1]);
                outB[jh][t] = f2h2(d[2], d[3]);
            } else if (nt < 18) {
                if (na < N) gbias[na * 8 + j] = f2h2(d[0], d[1]);
                if (nb < N) gbias[nb * 8 + j] = f2h2(d[2], d[3]);
            } else {
                float c0 = jh ? br8 : br0;
                float c1 = jh ? br9 : br1;
                if (na < N)
                    *(float2*)(agg_buf + (size_t)na * 16 + 2 * j) =
                        make_float2(d[0] + c0, d[1] + c1);
                if (nb < N)
                    *(float2*)(agg_buf + (size_t)nb * 16 + 2 * j) =
                        make_float2(d[2] + c0, d[3] + c1);
            }
        }

#pragma unroll
        for (int jh = 0; jh < 2; jh++) {
            int j = m + 4 * jh;
            if (na < N) {
                uint4* p = (uint4*)(g8 + (size_t)na * 128 + j * 16);
                p[0] = make_uint4(outA[jh][0], outA[jh][1], outA[jh][2], outA[jh][3]);
                p[1] = make_uint4(outA[jh][4], outA[jh][5], outA[jh][6], outA[jh][7]);
            }
            if (nb < N) {
                uint4* p = (uint4*)(g8 + (size_t)nb * 128 + j * 16);
                p[0] = make_uint4(outB[jh][0], outB[jh][1], outB[jh][2], outB[jh][3]);
                p[1] = make_uint4(outB[jh][4], outB[jh][5], outB[jh][6], outB[jh][7]);
            }
        }
    }
}

// ---------------------------------------------------------------------------
// Kernel E: 2 edges per thread, 8 lanes per edge (lane j owns h = {2j,2j+1}).
// Two independent gather->dot->red chains per thread (doubled MLP).
// PDL: independent loads hoisted above cudaGridDependencySynchronize().
// ---------------------------------------------------------------------------
__global__ void __launch_bounds__(256) edge_kernel(const float* __restrict__ e,
                                                   const int* __restrict__ src,
                                                   const int* __restrict__ dst,
                                                   int E)
{
    if (blockIdx.x == 0 && threadIdx.x < 17) {
        if (threadIdx.x < 16) pooled_bits[threadIdx.x] = 0u;  // = 0.0f
        else                  finish_count = 0u;
    }

    int t = blockIdx.x * 256 + threadIdx.x;
    int grp = t >> 3;            // pair index
    int j = t & 7;
    int g0 = grp * 2, g1 = grp * 2 + 1;
    bool act0 = (g0 < E), act1 = (g1 < E);

    int sn0 = 0, dn0 = 0, sn1 = 0, dn1 = 0;
    float4 e00 = make_float4(0.f,0.f,0.f,0.f), e01 = e00, e10 = e00, e11 = e00;
    if (act0) {
        sn0 = __ldg(src + g0);  dn0 = __ldg(dst + g0);
        const float4* ep = (const float4*)e + (size_t)g0 * 2;
        e00 = __ldg(ep);  e01 = __ldg(ep + 1);
    }
    if (act1) {
        sn1 = __ldg(src + g1);  dn1 = __ldg(dst + g1);
        const float4* ep = (const float4*)e + (size_t)g1 * 2;
        e10 = __ldg(ep);  e11 = __ldg(ep + 1);
    }

    cudaGridDependencySynchronize();
    if (!act0) return;

    // chain 0
    const uint4* gp0 = (const uint4*)(g8 + (size_t)sn0 * 128 + j * 16);
    uint4 a0v = __ldg(gp0);
    uint4 b0v = __ldg(gp0 + 1);
    unsigned gb0 = __ldg(gbias + sn0 * 8 + j);
    // chain 1 (issued before consuming chain 0 -> overlapped latency)
    uint4 a1v, b1v; unsigned gb1 = 0;
    if (act1) {
        const uint4* gp1 = (const uint4*)(g8 + (size_t)sn1 * 128 + j * 16);
        a1v = __ldg(gp1);
        b1v = __ldg(gp1 + 1);
        gb1 = __ldg(gbias + sn1 * 8 + j);
    }

    {
        float2 w0 = __half22float2(*(__half2*)&a0v.x);
        float2 w1 = __half22float2(*(__half2*)&a0v.y);
        float2 w2 = __half22float2(*(__half2*)&a0v.z);
        float2 w3 = __half22float2(*(__half2*)&a0v.w);
        float2 w4 = __half22float2(*(__half2*)&b0v.x);
        float2 w5 = __half22float2(*(__half2*)&b0v.y);
        float2 w6 = __half22float2(*(__half2*)&b0v.z);
        float2 w7 = __half22float2(*(__half2*)&b0v.w);
        float2 wb = __half22float2(*(__half2*)&gb0);
        float ax = wb.x, ay = wb.y;
        ax = fmaf(e00.x, w0.x, ax);  ay = fmaf(e00.x, w0.y, ay);
        ax = fmaf(e00.y, w1.x, ax);  ay = fmaf(e00.y, w1.y, ay);
        ax = fmaf(e00.z, w2.x, ax);  ay = fmaf(e00.z, w2.y, ay);
        ax = fmaf(e00.w, w3.x, ax);  ay = fmaf(e00.w, w3.y, ay);
        ax = fmaf(e01.x, w4.x, ax);  ay = fmaf(e01.x, w4.y, ay);
        ax = fmaf(e01.y, w5.x, ax);  ay = fmaf(e01.y, w5.y, ay);
        ax = fmaf(e01.z, w6.x, ax);  ay = fmaf(e01.z, w6.y, ay);
        ax = fmaf(e01.w, w7.x, ax);  ay = fmaf(e01.w, w7.y, ay);
        float* o = agg_buf + (size_t)dn0 * 16 + 2 * j;
        asm volatile("red.global.add.v2.f32 [%0], {%1, %2};"
                     :: "l"(o), "f"(ax), "f"(ay) : "memory");
    }

    if (act1) {
        float2 w0 = __half22float2(*(__half2*)&a1v.x);
        float2 w1 = __half22float2(*(__half2*)&a1v.y);
        float2 w2 = __half22float2(*(__half2*)&a1v.z);
        float2 w3 = __half22float2(*(__half2*)&a1v.w);
        float2 w4 = __half22float2(*(__half2*)&b1v.x);
        float2 w5 = __half22float2(*(__half2*)&b1v.y);
        float2 w6 = __half22float2(*(__half2*)&b1v.z);
        float2 w7 = __half22float2(*(__half2*)&b1v.w);
        float2 wb = __half22float2(*(__half2*)&gb1);
        float ax = wb.x, ay = wb.y;
        ax = fmaf(e10.x, w0.x, ax);  ay = fmaf(e10.x, w0.y, ay);
        ax = fmaf(e10.y, w1.x, ax);  ay = fmaf(e10.y, w1.y, ay);
        ax = fmaf(e10.z, w2.x, ax);  ay = fmaf(e10.z, w2.y, ay);
        ax = fmaf(e10.w, w3.x, ax);  ay = fmaf(e10.w, w3.y, ay);
        ax = fmaf(e11.x, w4.x, ax);  ay = fmaf(e11.x, w4.y, ay);
        ax = fmaf(e11.y, w5.x, ax);  ay = fmaf(e11.y, w5.y, ay);
        ax = fmaf(e11.z, w6.x, ax);  ay = fmaf(e11.z, w6.y, ay);
        ax = fmaf(e11.w, w7.x, ax);  ay = fmaf(e11.w, w7.y, ay);
        float* o = agg_buf + (size_t)dn1 * 16 + 2 * j;
        asm volatile("red.global.add.v2.f32 [%0], {%1, %2};"
                     :: "l"(o), "f"(ax), "f"(ay) : "memory");
    }
}

// ---------------------------------------------------------------------------
// Kernel C: relu + max-pool; BN deferred past the pool (sc >= 0 here).
// ---------------------------------------------------------------------------
__global__ void __launch_bounds__(256) node_post(const float* __restrict__ gamma,
                                                 const float* __restrict__ beta,
                                                 const float* __restrict__ mmean,
                                                 const float* __restrict__ mvar,
                                                 const float* __restrict__ Wd,
                                                 const float* __restrict__ bd,
                                                 float* __restrict__ out,
                                                 int N)
{
    __shared__ float wmax[8][16];
    __shared__ bool is_last;
    int n = blockIdx.x * 256 + threadIdx.x;
    int l = threadIdx.x & 31;

    cudaGridDependencySynchronize();   // wait for all edge reds

    float v[16];
    if (n < N) {
        const float4* ar = (const float4*)(agg_buf + (size_t)n * 16);
#pragma unroll
        for (int q = 0; q < 4; q++) {
            float4 a = __ldcg(ar + q);
            v[4 * q + 0] = fmaxf(a.x, 0.0f); v[4 * q + 1] = fmaxf(a.y, 0.0f);
            v[4 * q + 2] = fmaxf(a.z, 0.0f); v[4 * q + 3] = fmaxf(a.w, 0.0f);
        }
    } else {
#pragma unroll
        for (int h = 0; h < 16; h++) v[h] = 0.0f;
    }

    {
        float r[16];
#pragma unroll
        for (int i = 0; i < 16; i++) r[i] = __shfl_xor_sync(0xffffffffu, v[i], 16);
        if (l & 16) {
#pragma unroll
            for (int i = 0; i < 8; i++) v[i] = fmaxf(v[i + 8], r[i + 8]);
        } else {
#pragma unroll
            for (int i = 0; i < 8; i++) v[i] = fmaxf(v[i], r[i]);
        }
    }
    {
        float r[8];
#pragma unroll
        for (int i = 0; i < 8; i++) r[i] = __shfl_xor_sync(0xffffffffu, v[i], 8);
        if (l & 8) {
#pragma unroll
            for (int i = 0; i < 4; i++) v[i] = fmaxf(v[i + 4], r[i + 4]);
        } else {
#pragma unroll
            for (int i = 0; i < 4; i++) v[i] = fmaxf(v[i], r[i]);
        }
    }
    {
        float r[4];
#pragma unroll
        for (int i = 0; i < 4; i++) r[i] = __shfl_xor_sync(0xffffffffu, v[i], 4);
        if (l & 4) {
            v[0] = fmaxf(v[2], r[2]); v[1] = fmaxf(v[3], r[3]);
        } else {
            v[0] = fmaxf(v[0], r[0]); v[1] = fmaxf(v[1], r[1]);
        }
    }
    {
        float r0 = __shfl_xor_sync(0xffffffffu, v[0], 2);
        float r1 = __shfl_xor_sync(0xffffffffu, v[1], 2);
        v[0] = (l & 2) ? fmaxf(v[1], r1) : fmaxf(v[0], r0);
    }
    v[0] = fmaxf(v[0], __shfl_xor_sync(0xffffffffu, v[0], 1));

    int wid = threadIdx.x >> 5;
    if ((l & 1) == 0) wmax[wid][(l >> 1) & 15] = v[0];
    __syncthreads();

    if (threadIdx.x < 16) {
        float m = wmax[0][threadIdx.x];
#pragma unroll
        for (int w2 = 1; w2 < 8; w2++) m = fmaxf(m, wmax[w2][threadIdx.x]);
        atomicMax(&pooled_bits[threadIdx.x], __float_as_uint(m));
    }

    __threadfence();
    if (threadIdx.x == 0) {
        unsigned c = atomicAdd(&finish_count, 1u);
        is_last = (c == gridDim.x - 1);
    }
    __syncthreads();
    if (!is_last) return;

    __threadfence();
    __shared__ float pooled[16];
    if (threadIdx.x < 16) {
        int h = threadIdx.x;
        unsigned k = atomicAdd(&pooled_bits[h], 0u);
        float raw = __uint_as_float(k);
        float sc = gamma[h] * rsqrtf(mvar[h] + 1e-3f);
        pooled[h] = raw * sc + (beta[h] - mmean[h] * sc);
    }
    __syncthreads();
    if (threadIdx.x < 3) {
        float s = bd[threadIdx.x];
#pragma unroll
        for (int h = 0; h < 16; h++) s += pooled[h] * Wd[h * 3 + threadIdx.x];
        out[threadIdx.x] = s;
    }
}

// ---------------------------------------------------------------------------
extern "C" void kernel_launch(void* const* d_in, const int* in_sizes, int n_in,
                              void* d_out, int out_size)
{
    const float* x     = (const float*)d_in[0];
    const float* e     = (const float*)d_in[1];
    const int*   src   = (const int*)d_in[2];
    const int*   dst   = (const int*)d_in[3];
    const float* Wk    = (const float*)d_in[4];
    const float* bk    = (const float*)d_in[5];
    const float* Wr    = (const float*)d_in[6];
    const float* br    = (const float*)d_in[7];
    const float* gamma = (const float*)d_in[8];
    const float* beta  = (const float*)d_in[9];
    const float* mmean = (const float*)d_in[10];
    const float* mvar  = (const float*)d_in[11];
    const float* Wd    = (const float*)d_in[12];
    const float* bd    = (const float*)d_in[13];

    int N = in_sizes[0] / 16;   // F = 16
    int E = in_sizes[2];

    node_pre<<<PRE_BLOCKS, 512>>>(x, Wk, bk, Wr, br, N);

    {
        cudaLaunchConfig_t cfg = {};
        cudaLaunchAttribute attr[1];
        attr[0].id = cudaLaunchAttributeProgrammaticStreamSerialization;
        attr[0].val.programmaticStreamSerializationAllowed = 1;
        cfg.gridDim  = dim3((unsigned)((E * 4 + 255) / 256));
        cfg.blockDim = dim3(256);
        cfg.attrs = attr;
        cfg.numAttrs = 1;
        cudaLaunchKernelEx(&cfg, edge_kernel, e, src, dst, E);
    }

    {
        cudaLaunchConfig_t cfg = {};
        cudaLaunchAttribute attr[1];
        attr[0].id = cudaLaunchAttributeProgrammaticStreamSerialization;
        attr[0].val.programmaticStreamSerializationAllowed = 1;
        cfg.gridDim  = dim3(148);
        cfg.blockDim = dim3(256);
        cfg.attrs = attr;
        cfg.numAttrs = 1;
        cudaLaunchKernelEx(&cfg, node_post, gamma, beta, mmean, mvar, Wd, bd,
                           (float*)d_out, N);
    }
}

// round 16
// speedup vs baseline: 1.1479x; 1.1479x over previous
#include <cuda_runtime.h>
#include <cuda_fp16.h>

// Problem dims (fixed by dataset): N=30000, F=16, S=8, H=16, E=300000
#define NMAX 30080
#define PRE_BLOCKS 148

// g, line-split j-major layout (256 B per node row):
//   bytes [  0..127]: lane chunks c0 = slices t0..3 for j=0..7, 16 B each at j*16
//   bytes [128..255]: lane chunks c1 = slices t4..7 for j=0..7, 16 B each
// -> each edge-gather LDG.128 touches exactly ONE 128B line per row.
__device__ __half   g8[(size_t)NMAX * 128];
__device__ unsigned gbias[(size_t)NMAX * 8];
__device__ float    agg_buf[(size_t)NMAX * 16];
__device__ unsigned pooled_bits[16];   // raw float bits of max(relu(agg)) >= 0
__device__ unsigned finish_count;

__device__ __forceinline__ void mma16816(float d[4],
    unsigned a0, unsigned a1, unsigned a2, unsigned a3,
    unsigned b0, unsigned b1)
{
    float z = 0.0f;
    asm("mma.sync.aligned.m16n8k16.row.col.f32.f16.f16.f32 "
        "{%0,%1,%2,%3}, {%4,%5,%6,%7}, {%8,%9}, {%10,%11,%12,%13};"
        : "=f"(d[0]), "=f"(d[1]), "=f"(d[2]), "=f"(d[3])
        : "r"(a0), "r"(a1), "r"(a2), "r"(a3), "r"(b0), "r"(b1),
          "f"(z), "f"(z), "f"(z), "f"(z));
}

__device__ __forceinline__ unsigned f2h2(float lo, float hi)
{
    __half2 h = __floats2half2_rn(lo, hi);
    return *(unsigned*)&h;
}

// ---------------------------------------------------------------------------
// Kernel P (HMMA): g[N x 160] = x[N x 16] @ Wtilde[16 x 160], fp16 in/fp32 acc.
// 148 blocks x 16 warps; warp (b,w) handles slab b + 148w -> <= 1 slab each.
// ---------------------------------------------------------------------------
struct AFrag { unsigned a0, a1, a2, a3; int na, nb; };

__device__ __forceinline__ AFrag load_afrag(const float2* X2, int n0, int r,
                                            int m, int N)
{
    AFrag f;
    f.na = n0 + r; f.nb = n0 + r + 8;
    int nac = (f.na < N) ? f.na : N - 1;
    int nbc = (f.nb < N) ? f.nb : N - 1;
    float2 xa0 = __ldg(X2 + (size_t)nac * 8 + m);
    float2 xa2 = __ldg(X2 + (size_t)nac * 8 + m + 4);
    float2 xa1 = __ldg(X2 + (size_t)nbc * 8 + m);
    float2 xa3 = __ldg(X2 + (size_t)nbc * 8 + m + 4);
    f.a0 = f2h2(xa0.x, xa0.y);
    f.a1 = f2h2(xa1.x, xa1.y);
    f.a2 = f2h2(xa2.x, xa2.y);
    f.a3 = f2h2(xa3.x, xa3.y);
    return f;
}

__global__ void __launch_bounds__(512) node_pre(const float* __restrict__ x,
                                                const float* __restrict__ Wk,
                                                const float* __restrict__ bk,
                                                const float* __restrict__ Wr,
                                                const float* __restrict__ br,
                                                int N)
{
    __shared__ __half Whs[160 * 18];                 // [c][f], stride 18 (pad)

    int tid = threadIdx.x;
    int w = tid >> 5;
    int l = tid & 31;
    int r = l >> 2;
    int m = l & 3;

    int nslabs = (N + 15) >> 4;
    const float2* X2 = (const float2*)x;

    int slab0 = blockIdx.x + PRE_BLOCKS * w;
    AFrag af;
    if (slab0 < nslabs) af = load_afrag(X2, slab0 * 16, r, m, N);

    for (int i = tid; i < 2560; i += 512) {
        int c = i >> 4, f = i & 15;
        int t = c >> 4, h = c & 15;
        float v = (t < 8) ? Wk[t * 256 + f * 16 + h]
                : (t == 8) ? bk[f * 16 + h] : Wr[f * 16 + h];
        Whs[c * 18 + f] = __float2half_rn(v);
    }
    __syncthreads();

    float br0 = br[2 * m], br1 = br[2 * m + 1];
    float br8 = br[8 + 2 * m], br9 = br[9 + 2 * m];

    for (int slab = slab0; slab < nslabs; slab += PRE_BLOCKS * 16) {
        if (slab != slab0) af = load_afrag(X2, slab * 16, r, m, N);
        int na = af.na, nb = af.nb;

        unsigned outA[2][8], outB[2][8];

#pragma unroll
        for (int nt = 0; nt < 20; nt++) {
            int c = nt * 8 + r;
            unsigned b0 = *(const unsigned*)&Whs[c * 18 + 2 * m];
            unsigned b1 = *(const unsigned*)&Whs[c * 18 + 2 * m + 8];
            float d[4];
            mma16816(d, af.a0, af.a1, af.a2, af.a3, b0, b1);
            int jh = nt & 1;
            int j  = m + 4 * jh;
            if (nt < 16) {
                int t = nt >> 1;
                outA[jh][t] = f2h2(d[0], d[1]);
                outB[jh][t] = f2h2(d[2], d[3]);
            } else if (nt < 18) {
                if (na < N) gbias[na * 8 + j] = f2h2(d[0], d[1]);
                if (nb < N) gbias[nb * 8 + j] = f2h2(d[2], d[3]);
            } else {
                float c0 = jh ? br8 : br0;
                float c1 = jh ? br9 : br1;
                if (na < N)
                    *(float2*)(agg_buf + (size_t)na * 16 + 2 * j) =
                        make_float2(d[0] + c0, d[1] + c1);
                if (nb < N)
                    *(float2*)(agg_buf + (size_t)nb * 16 + 2 * j) =
                        make_float2(d[2] + c0, d[3] + c1);
            }
        }

        // Line-split stores: c0 chunk -> line 0 at j*16B, c1 -> line 1.
#pragma unroll
        for (int jh = 0; jh < 2; jh++) {
            int j = m + 4 * jh;
            if (na < N) {
                uint4* p = (uint4*)(g8 + (size_t)na * 128 + j * 8);
                p[0] = make_uint4(outA[jh][0], outA[jh][1], outA[jh][2], outA[jh][3]);
                p[8] = make_uint4(outA[jh][4], outA[jh][5], outA[jh][6], outA[jh][7]);
            }
            if (nb < N) {
                uint4* p = (uint4*)(g8 + (size_t)nb * 128 + j * 8);
                p[0] = make_uint4(outB[jh][0], outB[jh][1], outB[jh][2], outB[jh][3]);
                p[8] = make_uint4(outB[jh][4], outB[jh][5], outB[jh][6], outB[jh][7]);
            }
        }
    }
}

// ---------------------------------------------------------------------------
// Kernel E: per-edge gather + dot + red.v2 scatter.
// 8 lanes per edge; with the line-split layout, each of the two g LDG.128
// instructions touches exactly one 128B line per source row.
// PDL: independent loads hoisted above cudaGridDependencySynchronize().
// ---------------------------------------------------------------------------
__global__ void __launch_bounds__(256) edge_kernel(const float* __restrict__ e,
                                                   const int* __restrict__ src,
                                                   const int* __restrict__ dst,
                                                   int E)
{
    if (blockIdx.x == 0 && threadIdx.x < 17) {
        if (threadIdx.x < 16) pooled_bits[threadIdx.x] = 0u;  // = 0.0f
        else                  finish_count = 0u;
    }

    int t = blockIdx.x * 256 + threadIdx.x;
    int gid = t >> 3;
    bool act = (gid < E);
    int j = t & 7;

    int sn = 0, dn = 0;
    float4 e0 = make_float4(0.f, 0.f, 0.f, 0.f), e1 = e0;
    if (act) {
        sn = __ldg(src + gid);
        dn = __ldg(dst + gid);
        const float4* ep = (const float4*)e + (size_t)gid * 2;
        e0 = __ldg(ep);
        e1 = __ldg(ep + 1);
    }

    cudaGridDependencySynchronize();
    if (!act) return;

    const uint4* gp = (const uint4*)(g8 + (size_t)sn * 128 + j * 8);
    uint4 a = __ldg(gp);          // line 0: slices t0..3
    uint4 b = __ldg(gp + 8);      // line 1: slices t4..7
    unsigned gb = __ldg(gbias + sn * 8 + j);

    float2 w0 = __half22float2(*(__half2*)&a.x);
    float2 w1 = __half22float2(*(__half2*)&a.y);
    float2 w2 = __half22float2(*(__half2*)&a.z);
    float2 w3 = __half22float2(*(__half2*)&a.w);
    float2 w4 = __half22float2(*(__half2*)&b.x);
    float2 w5 = __half22float2(*(__half2*)&b.y);
    float2 w6 = __half22float2(*(__half2*)&b.z);
    float2 w7 = __half22float2(*(__half2*)&b.w);
    float2 wb = __half22float2(*(__half2*)&gb);

    float ax = wb.x, ay = wb.y;
    ax = fmaf(e0.x, w0.x, ax);  ay = fmaf(e0.x, w0.y, ay);
    ax = fmaf(e0.y, w1.x, ax);  ay = fmaf(e0.y, w1.y, ay);
    ax = fmaf(e0.z, w2.x, ax);  ay = fmaf(e0.z, w2.y, ay);
    ax = fmaf(e0.w, w3.x, ax);  ay = fmaf(e0.w, w3.y, ay);
    ax = fmaf(e1.x, w4.x, ax);  ay = fmaf(e1.x, w4.y, ay);
    ax = fmaf(e1.y, w5.x, ax);  ay = fmaf(e1.y, w5.y, ay);
    ax = fmaf(e1.z, w6.x, ax);  ay = fmaf(e1.z, w6.y, ay);
    ax = fmaf(e1.w, w7.x, ax);  ay = fmaf(e1.w, w7.y, ay);

    float* o = agg_buf + (size_t)dn * 16 + 2 * j;
    asm volatile("red.global.add.v2.f32 [%0], {%1, %2};"
                 :: "l"(o), "f"(ax), "f"(ay) : "memory");
}

// ---------------------------------------------------------------------------
// Kernel C: relu + max-pool; BN deferred past the pool (sc >= 0 here).
// ---------------------------------------------------------------------------
__global__ void __launch_bounds__(256) node_post(const float* __restrict__ gamma,
                                                 const float* __restrict__ beta,
                                                 const float* __restrict__ mmean,
                                                 const float* __restrict__ mvar,
                                                 const float* __restrict__ Wd,
                                                 const float* __restrict__ bd,
                                                 float* __restrict__ out,
                                                 int N)
{
    __shared__ float wmax[8][16];
    __shared__ bool is_last;
    int n = blockIdx.x * 256 + threadIdx.x;
    int l = threadIdx.x & 31;

    cudaGridDependencySynchronize();   // wait for all edge reds

    float v[16];
    if (n < N) {
        const float4* ar = (const float4*)(agg_buf + (size_t)n * 16);
#pragma unroll
        for (int q = 0; q < 4; q++) {
            float4 a = __ldcg(ar + q);
            v[4 * q + 0] = fmaxf(a.x, 0.0f); v[4 * q + 1] = fmaxf(a.y, 0.0f);
            v[4 * q + 2] = fmaxf(a.z, 0.0f); v[4 * q + 3] = fmaxf(a.w, 0.0f);
        }
    } else {
#pragma unroll
        for (int h = 0; h < 16; h++) v[h] = 0.0f;
    }

    {
        float r[16];
#pragma unroll
        for (int i = 0; i < 16; i++) r[i] = __shfl_xor_sync(0xffffffffu, v[i], 16);
        if (l & 16) {
#pragma unroll
            for (int i = 0; i < 8; i++) v[i] = fmaxf(v[i + 8], r[i + 8]);
        } else {
#pragma unroll
            for (int i = 0; i < 8; i++) v[i] = fmaxf(v[i], r[i]);
        }
    }
    {
        float r[8];
#pragma unroll
        for (int i = 0; i < 8; i++) r[i] = __shfl_xor_sync(0xffffffffu, v[i], 8);
        if (l & 8) {
#pragma unroll
            for (int i = 0; i < 4; i++) v[i] = fmaxf(v[i + 4], r[i + 4]);
        } else {
#pragma unroll
            for (int i = 0; i < 4; i++) v[i] = fmaxf(v[i], r[i]);
        }
    }
    {
        float r[4];
#pragma unroll
        for (int i = 0; i < 4; i++) r[i] = __shfl_xor_sync(0xffffffffu, v[i], 4);
        if (l & 4) {
            v[0] = fmaxf(v[2], r[2]); v[1] = fmaxf(v[3], r[3]);
        } else {
            v[0] = fmaxf(v[0], r[0]); v[1] = fmaxf(v[1], r[1]);
        }
    }
    {
        float r0 = __shfl_xor_sync(0xffffffffu, v[0], 2);
        float r1 = __shfl_xor_sync(0xffffffffu, v[1], 2);
        v[0] = (l & 2) ? fmaxf(v[1], r1) : fmaxf(v[0], r0);
    }
    v[0] = fmaxf(v[0], __shfl_xor_sync(0xffffffffu, v[0], 1));

    int wid = threadIdx.x >> 5;
    if ((l & 1) == 0) wmax[wid][(l >> 1) & 15] = v[0];
    __syncthreads();

    if (threadIdx.x < 16) {
        float m = wmax[0][threadIdx.x];
#pragma unroll
        for (int w2 = 1; w2 < 8; w2++) m = fmaxf(m, wmax[w2][threadIdx.x]);
        atomicMax(&pooled_bits[threadIdx.x], __float_as_uint(m));
    }

    __threadfence();
    if (threadIdx.x == 0) {
        unsigned c = atomicAdd(&finish_count, 1u);
        is_last = (c == gridDim.x - 1);
    }
    __syncthreads();
    if (!is_last) return;

    __threadfence();
    __shared__ float pooled[16];
    if (threadIdx.x < 16) {
        int h = threadIdx.x;
        unsigned k = atomicAdd(&pooled_bits[h], 0u);
        float raw = __uint_as_float(k);
        float sc = gamma[h] * rsqrtf(mvar[h] + 1e-3f);
        pooled[h] = raw * sc + (beta[h] - mmean[h] * sc);
    }
    __syncthreads();
    if (threadIdx.x < 3) {
        float s = bd[threadIdx.x];
#pragma unroll
        for (int h = 0; h < 16; h++) s += pooled[h] * Wd[h * 3 + threadIdx.x];
        out[threadIdx.x] = s;
    }
}

// ---------------------------------------------------------------------------
extern "C" void kernel_launch(void* const* d_in, const int* in_sizes, int n_in,
                              void* d_out, int out_size)
{
    const float* x     = (const float*)d_in[0];
    const float* e     = (const float*)d_in[1];
    const int*   src   = (const int*)d_in[2];
    const int*   dst   = (const int*)d_in[3];
    const float* Wk    = (const float*)d_in[4];
    const float* bk    = (const float*)d_in[5];
    const float* Wr    = (const float*)d_in[6];
    const float* br    = (const float*)d_in[7];
    const float* gamma = (const float*)d_in[8];
    const float* beta  = (const float*)d_in[9];
    const float* mmean = (const float*)d_in[10];
    const float* mvar  = (const float*)d_in[11];
    const float* Wd    = (const float*)d_in[12];
    const float* bd    = (const float*)d_in[13];

    int N = in_sizes[0] / 16;   // F = 16
    int E = in_sizes[2];

    node_pre<<<PRE_BLOCKS, 512>>>(x, Wk, bk, Wr, br, N);

    {
        cudaLaunchConfig_t cfg = {};
        cudaLaunchAttribute attr[1];
        attr[0].id = cudaLaunchAttributeProgrammaticStreamSerialization;
        attr[0].val.programmaticStreamSerializationAllowed = 1;
        cfg.gridDim  = dim3((unsigned)((E * 8 + 255) / 256));
        cfg.blockDim = dim3(256);
        cfg.attrs = attr;
        cfg.numAttrs = 1;
        cudaLaunchKernelEx(&cfg, edge_kernel, e, src, dst, E);
    }

    {
        cudaLaunchConfig_t cfg = {};
        cudaLaunchAttribute attr[1];
        attr[0].id = cudaLaunchAttributeProgrammaticStreamSerialization;
        attr[0].val.programmaticStreamSerializationAllowed = 1;
        cfg.gridDim  = dim3(148);
        cfg.blockDim = dim3(256);
        cfg.attrs = attr;
        cfg.numAttrs = 1;
        cudaLaunchKernelEx(&cfg, node_post, gamma, beta, mmean, mvar, Wd, bd,
                           (float*)d_out, N);
    }
}